// round 2
// baseline (speedup 1.0000x reference)
#include <cuda_runtime.h>

// DeepAttensionModule — SeFT cumulative set attention, restructured:
//  k_prep : fold query into W_key  -> Wkq[95,4], bq[4]
//  k_feat : per-token psi/phi MLPs; emit phi[32], a[4]=psi·Wkq2, xq[4]=x·Wkq1
//  k_scan : per (b,head) warp: scalar prefix (A,Sm) -> pre; online softmax (M,S,V[32]) -> agg
//  k_rho  : per-token rho MLP -> out

#define BATCH 16
#define SEQ   1024
#define NTOK  (BATCH*SEQ)
#define NH    4
#define KEYIN 95
#define NEG_BIG (-3.402823466e38f)

__device__ float g_phi[NTOK*32];
__device__ float g_a[NTOK*4];
__device__ float g_xq[NTOK*4];
__device__ float g_agg[NTOK*128];
__device__ float g_Wkq[KEYIN*4];
__device__ float g_bq[4];

// ---------------------------------------------------------------- k_prep
__global__ void k_prep(const float* __restrict__ Wk, const float* __restrict__ bk,
                       const float* __restrict__ q) {
    int idx = threadIdx.x;
    if (idx < KEYIN*4) {
        int s = idx >> 2, h = idx & 3;
        float acc = 0.f;
        #pragma unroll
        for (int d = 0; d < 32; d++) acc += Wk[s*128 + h*32 + d] * q[h*32 + d];
        g_Wkq[idx] = acc;                      // layout [s][h]
    } else if (idx < KEYIN*4 + 4) {
        int h = idx - KEYIN*4;
        float acc = 0.f;
        #pragma unroll
        for (int d = 0; d < 32; d++) acc += bk[h*32 + d] * q[h*32 + d];
        g_bq[h] = acc;
    }
}

// ---------------------------------------------------------------- k_feat
__global__ void __launch_bounds__(128) k_feat(
    const float* __restrict__ times, const float* __restrict__ values,
    const int*   __restrict__ meas,  const float* __restrict__ mask,
    const float* __restrict__ Wp1, const float* __restrict__ bp1,
    const float* __restrict__ Wp2, const float* __restrict__ bp2,
    const float* __restrict__ Wf1, const float* __restrict__ bf1,
    const float* __restrict__ Wf2, const float* __restrict__ bf2)
{
    __shared__ float sWp1[9*64];     // rows 0..8 (te + value)
    __shared__ float sMp1[64*22];    // transposed one-hot rows: [j][m] = Wp1[(9+m)*64+j]
    __shared__ float sWp2[64*64];
    __shared__ float sWf1[9*32];
    __shared__ float sMf1[32*22];
    __shared__ float sWf2[32*32];
    __shared__ float sWkq[KEYIN*4];
    __shared__ float sbp1[64], sbp2[64], sbf1[32], sbf2[32];

    int tid = threadIdx.x;
    for (int i = tid; i < 9*64;  i += 128) sWp1[i] = Wp1[i];
    for (int i = tid; i < 64*22; i += 128) { int j = i/22, m = i%22; sMp1[i] = Wp1[(9+m)*64 + j]; }
    for (int i = tid; i < 64*64; i += 128) sWp2[i] = Wp2[i];
    for (int i = tid; i < 9*32;  i += 128) sWf1[i] = Wf1[i];
    for (int i = tid; i < 32*22; i += 128) { int j = i/22, m = i%22; sMf1[i] = Wf1[(9+m)*32 + j]; }
    for (int i = tid; i < 32*32; i += 128) sWf2[i] = Wf2[i];
    for (int i = tid; i < KEYIN*4; i += 128) sWkq[i] = g_Wkq[i];
    if (tid < 64) { sbp1[tid] = bp1[tid]; sbp2[tid] = bp2[tid]; }
    if (tid < 32) { sbf1[tid] = bf1[tid]; sbf2[tid] = bf2[tid]; }
    __syncthreads();

    int idx = blockIdx.x*128 + tid;
    float t  = times[idx];
    float v  = values[idx];
    float mk = mask[idx];
    int   ms = meas[idx];

    float x9[9];
    x9[0] = sinf(t);          x9[1] = cosf(t);
    x9[2] = sinf(t*0.1f);     x9[3] = cosf(t*0.1f);
    x9[4] = sinf(t*0.01f);    x9[5] = cosf(t*0.01f);
    x9[6] = sinf(t*0.001f);   x9[7] = cosf(t*0.001f);
    x9[8] = v;

    // ---- psi layer 1 ----
    float acc[64];
    #pragma unroll
    for (int j = 0; j < 64; j++) acc[j] = sbp1[j];
    const float4* sWp1v = (const float4*)sWp1;
    #pragma unroll
    for (int r = 0; r < 9; r++) {
        float s = x9[r];
        #pragma unroll
        for (int j4 = 0; j4 < 16; j4++) {
            float4 w = sWp1v[r*16 + j4];
            acc[j4*4+0] += s*w.x; acc[j4*4+1] += s*w.y;
            acc[j4*4+2] += s*w.z; acc[j4*4+3] += s*w.w;
        }
    }
    if (ms > 0) {
        int m = ms - 1;
        #pragma unroll
        for (int j = 0; j < 64; j++) acc[j] += sMp1[j*22 + m];
    }
    float h1[64];
    #pragma unroll
    for (int j = 0; j < 64; j++) h1[j] = fmaxf(acc[j], 0.f);

    // ---- psi layer 2, folded directly into a[4] = (psi*m)·Wkq2 ----
    #pragma unroll
    for (int j = 0; j < 64; j++) acc[j] = sbp2[j];
    const float4* sWp2v = (const float4*)sWp2;
    #pragma unroll 8
    for (int c = 0; c < 64; c++) {
        float s = h1[c];
        #pragma unroll
        for (int j4 = 0; j4 < 16; j4++) {
            float4 w = sWp2v[c*16 + j4];
            acc[j4*4+0] += s*w.x; acc[j4*4+1] += s*w.y;
            acc[j4*4+2] += s*w.z; acc[j4*4+3] += s*w.w;
        }
    }
    const float4* sWkqv = (const float4*)sWkq;
    float a0 = 0.f, a1 = 0.f, a2 = 0.f, a3 = 0.f;
    #pragma unroll
    for (int j = 0; j < 64; j++) {
        float ps = fmaxf(acc[j], 0.f) * mk;
        float4 wk = sWkqv[31 + j];
        a0 += ps*wk.x; a1 += ps*wk.y; a2 += ps*wk.z; a3 += ps*wk.w;
    }
    ((float4*)g_a)[idx] = make_float4(a0, a1, a2, a3);

    // ---- xq[4] = x·Wkq1 ----
    float q0 = 0.f, q1 = 0.f, q2 = 0.f, q3 = 0.f;
    #pragma unroll
    for (int r = 0; r < 9; r++) {
        float4 wk = sWkqv[r];
        q0 += x9[r]*wk.x; q1 += x9[r]*wk.y; q2 += x9[r]*wk.z; q3 += x9[r]*wk.w;
    }
    if (ms > 0) {
        float4 wk = sWkqv[8 + ms];
        q0 += wk.x; q1 += wk.y; q2 += wk.z; q3 += wk.w;
    }
    ((float4*)g_xq)[idx] = make_float4(q0, q1, q2, q3);

    // ---- phi MLP ----
    float f1[32];
    {
        float fa[32];
        #pragma unroll
        for (int j = 0; j < 32; j++) fa[j] = sbf1[j];
        const float4* sWf1v = (const float4*)sWf1;
        #pragma unroll
        for (int r = 0; r < 9; r++) {
            float s = x9[r];
            #pragma unroll
            for (int j4 = 0; j4 < 8; j4++) {
                float4 w = sWf1v[r*8 + j4];
                fa[j4*4+0] += s*w.x; fa[j4*4+1] += s*w.y;
                fa[j4*4+2] += s*w.z; fa[j4*4+3] += s*w.w;
            }
        }
        if (ms > 0) {
            int m = ms - 1;
            #pragma unroll
            for (int j = 0; j < 32; j++) fa[j] += sMf1[j*22 + m];
        }
        #pragma unroll
        for (int j = 0; j < 32; j++) f1[j] = fmaxf(fa[j], 0.f);
    }
    {
        float fa[32];
        #pragma unroll
        for (int j = 0; j < 32; j++) fa[j] = sbf2[j];
        const float4* sWf2v = (const float4*)sWf2;
        #pragma unroll 8
        for (int c = 0; c < 32; c++) {
            float s = f1[c];
            #pragma unroll
            for (int j4 = 0; j4 < 8; j4++) {
                float4 w = sWf2v[c*8 + j4];
                fa[j4*4+0] += s*w.x; fa[j4*4+1] += s*w.y;
                fa[j4*4+2] += s*w.z; fa[j4*4+3] += s*w.w;
            }
        }
        float4* phv = (float4*)(g_phi + (size_t)idx*32);
        #pragma unroll
        for (int j4 = 0; j4 < 8; j4++) {
            phv[j4] = make_float4(fmaxf(fa[j4*4+0],0.f)*mk, fmaxf(fa[j4*4+1],0.f)*mk,
                                  fmaxf(fa[j4*4+2],0.f)*mk, fmaxf(fa[j4*4+3],0.f)*mk);
        }
    }
}

// ---------------------------------------------------------------- k_scan
// one warp per (batch, head); lane = phi channel (PHI_W == 32)
__global__ void __launch_bounds__(32) k_scan(const float* __restrict__ mask) {
    int b = blockIdx.x >> 2;
    int h = blockIdx.x & 3;
    int lane = threadIdx.x;
    const float bq = g_bq[h];
    const float inv_sqrt = 0.17677669529663688f;   // 1/sqrt(32)

    float A = 0.f, Sm = 0.f;
    float M = NEG_BIG, S = 0.f, V = 0.f;
    int base = b * SEQ;

    for (int p = 0; p < SEQ; p++) {
        int idx = base + p;
        float ap  = g_a[idx*4 + h];
        float xqp = g_xq[idx*4 + h];
        float mkp = mask[idx];
        float ph  = g_phi[(size_t)idx*32 + lane];

        A  += ap;
        Sm += mkp;
        float pre = (xqp + bq + __fdividef(A, Sm)) * inv_sqrt;

        float nM = fmaxf(M, pre);
        float cs = __expf(M - nM);
        float w  = __expf(pre - nM);
        S = S*cs + w;
        V = V*cs + w*ph;
        M = nM;

        g_agg[(size_t)idx*128 + h*32 + lane] = __fdividef(V, S) * mkp;
    }
}

// ---------------------------------------------------------------- k_rho
__global__ void __launch_bounds__(128) k_rho(
    const float* __restrict__ W1, const float* __restrict__ b1,
    const float* __restrict__ W2, const float* __restrict__ b2,
    const float* __restrict__ mask, float* __restrict__ out)
{
    __shared__ float sA[128*33];
    __shared__ float sb1[64], sb2[64];
    int tid = threadIdx.x;
    if (tid < 64) { sb1[tid] = b1[tid]; sb2[tid] = b2[tid]; }

    int tok0 = blockIdx.x * 128;
    float acc[64];
    #pragma unroll
    for (int j = 0; j < 64; j++) acc[j] = 0.f;

    for (int kc = 0; kc < 4; kc++) {
        __syncthreads();
        // stage 128 tokens x 32 channels (coalesced global -> padded smem)
        #pragma unroll 4
        for (int r = 0; r < 32; r++) {
            int linear = r*128 + tid;
            int tk = linear >> 5, kk = linear & 31;
            sA[tk*33 + kk] = g_agg[(size_t)(tok0 + tk)*128 + kc*32 + kk];
        }
        __syncthreads();
        float rv[32];
        #pragma unroll
        for (int kk = 0; kk < 32; kk++) rv[kk] = sA[tid*33 + kk];
        #pragma unroll 4
        for (int kk = 0; kk < 32; kk++) {
            float s = rv[kk];
            const float4* w4 = (const float4*)&W1[(kc*32 + kk)*64];
            #pragma unroll
            for (int j4 = 0; j4 < 16; j4++) {
                float4 w = __ldg(&w4[j4]);
                acc[j4*4+0] += s*w.x; acc[j4*4+1] += s*w.y;
                acc[j4*4+2] += s*w.z; acc[j4*4+3] += s*w.w;
            }
        }
    }
    float hh[64];
    #pragma unroll
    for (int j = 0; j < 64; j++) hh[j] = fmaxf(acc[j] + sb1[j], 0.f);

    float mk = mask[tok0 + tid];
    float4* op = (float4*)(out + (size_t)(tok0 + tid)*64);

    #pragma unroll
    for (int half = 0; half < 2; half++) {
        float a2[32];
        #pragma unroll
        for (int j = 0; j < 32; j++) a2[j] = sb2[half*32 + j];
        #pragma unroll 4
        for (int c = 0; c < 64; c++) {
            float s = hh[c];
            const float4* w4 = (const float4*)&W2[c*64 + half*32];
            #pragma unroll
            for (int j4 = 0; j4 < 8; j4++) {
                float4 w = __ldg(&w4[j4]);
                a2[j4*4+0] += s*w.x; a2[j4*4+1] += s*w.y;
                a2[j4*4+2] += s*w.z; a2[j4*4+3] += s*w.w;
            }
        }
        #pragma unroll
        for (int j4 = 0; j4 < 8; j4++) {
            op[half*8 + j4] = make_float4(
                fmaxf(a2[j4*4+0],0.f)*mk, fmaxf(a2[j4*4+1],0.f)*mk,
                fmaxf(a2[j4*4+2],0.f)*mk, fmaxf(a2[j4*4+3],0.f)*mk);
        }
    }
}

// ---------------------------------------------------------------- launch
extern "C" void kernel_launch(void* const* d_in, const int* in_sizes, int n_in,
                              void* d_out, int out_size) {
    (void)in_sizes; (void)n_in; (void)out_size;
    const float* times  = (const float*)d_in[0];
    const float* values = (const float*)d_in[1];
    const int*   meas   = (const int*)  d_in[2];
    const float* mask   = (const float*)d_in[3];
    const float* Wp1 = (const float*)d_in[4];  const float* bp1 = (const float*)d_in[5];
    const float* Wp2 = (const float*)d_in[6];  const float* bp2 = (const float*)d_in[7];
    const float* Wk  = (const float*)d_in[8];  const float* bk  = (const float*)d_in[9];
    const float* q   = (const float*)d_in[10];
    const float* Wf1 = (const float*)d_in[11]; const float* bf1 = (const float*)d_in[12];
    const float* Wf2 = (const float*)d_in[13]; const float* bf2 = (const float*)d_in[14];
    const float* Wr1 = (const float*)d_in[15]; const float* br1 = (const float*)d_in[16];
    const float* Wr2 = (const float*)d_in[17]; const float* br2 = (const float*)d_in[18];
    float* out = (float*)d_out;

    k_prep<<<1, 384>>>(Wk, bk, q);
    k_feat<<<128, 128>>>(times, values, meas, mask,
                         Wp1, bp1, Wp2, bp2, Wf1, bf1, Wf2, bf2);
    k_scan<<<BATCH*NH, 32>>>(mask);
    k_rho<<<128, 128>>>(Wr1, br1, Wr2, br2, mask, out);
}

// round 3
// speedup vs baseline: 9.6765x; 9.6765x over previous
#include <cuda_runtime.h>

// DeepAttensionModule — SeFT cumulative set attention.
//  k_prep : fold query into W_key  -> Wkq[95,4], bq[4]
//  k_feat : per-token psi/phi MLPs; emit phi[32], a[4]=psi·Wkq2, xq[4]=x·Wkq1
//  k_scan : per (b,h) 1024-thread block: block-scan -> pre; chunked parallel
//           online-softmax scan (M,S,V[32] monoid) -> agg
//  k_rho  : per-token rho MLP (weights + act tile in smem) -> out

#define BATCH 16
#define SEQ   1024
#define NTOK  (BATCH*SEQ)
#define NH    4
#define KEYIN 95
#define NEG_BIG (-3.402823466e38f)

__device__ float g_phi[NTOK*32];
__device__ float g_a[NTOK*4];
__device__ float g_xq[NTOK*4];
__device__ float g_agg[NTOK*128];
__device__ float g_Wkq[KEYIN*4];
__device__ float g_bq[4];

// ---------------------------------------------------------------- k_prep
__global__ void k_prep(const float* __restrict__ Wk, const float* __restrict__ bk,
                       const float* __restrict__ q) {
    int idx = threadIdx.x;
    if (idx < KEYIN*4) {
        int s = idx >> 2, h = idx & 3;
        float acc = 0.f;
        #pragma unroll
        for (int d = 0; d < 32; d++) acc += Wk[s*128 + h*32 + d] * q[h*32 + d];
        g_Wkq[idx] = acc;                      // layout [s][h]
    } else if (idx < KEYIN*4 + 4) {
        int h = idx - KEYIN*4;
        float acc = 0.f;
        #pragma unroll
        for (int d = 0; d < 32; d++) acc += bk[h*32 + d] * q[h*32 + d];
        g_bq[h] = acc;
    }
}

// ---------------------------------------------------------------- k_feat
__global__ void __launch_bounds__(128) k_feat(
    const float* __restrict__ times, const float* __restrict__ values,
    const int*   __restrict__ meas,  const float* __restrict__ mask,
    const float* __restrict__ Wp1, const float* __restrict__ bp1,
    const float* __restrict__ Wp2, const float* __restrict__ bp2,
    const float* __restrict__ Wf1, const float* __restrict__ bf1,
    const float* __restrict__ Wf2, const float* __restrict__ bf2)
{
    __shared__ float sWp1[9*64];
    __shared__ float sMp1[64*22];
    __shared__ float sWp2[64*64];
    __shared__ float sWf1[9*32];
    __shared__ float sMf1[32*22];
    __shared__ float sWf2[32*32];
    __shared__ float sWkq[KEYIN*4];
    __shared__ float sbp1[64], sbp2[64], sbf1[32], sbf2[32];

    int tid = threadIdx.x;
    for (int i = tid; i < 9*64;  i += 128) sWp1[i] = Wp1[i];
    for (int i = tid; i < 64*22; i += 128) { int j = i/22, m = i%22; sMp1[i] = Wp1[(9+m)*64 + j]; }
    for (int i = tid; i < 64*64; i += 128) sWp2[i] = Wp2[i];
    for (int i = tid; i < 9*32;  i += 128) sWf1[i] = Wf1[i];
    for (int i = tid; i < 32*22; i += 128) { int j = i/22, m = i%22; sMf1[i] = Wf1[(9+m)*32 + j]; }
    for (int i = tid; i < 32*32; i += 128) sWf2[i] = Wf2[i];
    for (int i = tid; i < KEYIN*4; i += 128) sWkq[i] = g_Wkq[i];
    if (tid < 64) { sbp1[tid] = bp1[tid]; sbp2[tid] = bp2[tid]; }
    if (tid < 32) { sbf1[tid] = bf1[tid]; sbf2[tid] = bf2[tid]; }
    __syncthreads();

    int idx = blockIdx.x*128 + tid;
    float t  = times[idx];
    float v  = values[idx];
    float mk = mask[idx];
    int   ms = meas[idx];

    float x9[9];
    x9[0] = sinf(t);          x9[1] = cosf(t);
    x9[2] = sinf(t*0.1f);     x9[3] = cosf(t*0.1f);
    x9[4] = sinf(t*0.01f);    x9[5] = cosf(t*0.01f);
    x9[6] = sinf(t*0.001f);   x9[7] = cosf(t*0.001f);
    x9[8] = v;

    // ---- psi layer 1 ----
    float acc[64];
    #pragma unroll
    for (int j = 0; j < 64; j++) acc[j] = sbp1[j];
    const float4* sWp1v = (const float4*)sWp1;
    #pragma unroll
    for (int r = 0; r < 9; r++) {
        float s = x9[r];
        #pragma unroll
        for (int j4 = 0; j4 < 16; j4++) {
            float4 w = sWp1v[r*16 + j4];
            acc[j4*4+0] += s*w.x; acc[j4*4+1] += s*w.y;
            acc[j4*4+2] += s*w.z; acc[j4*4+3] += s*w.w;
        }
    }
    if (ms > 0) {
        int m = ms - 1;
        #pragma unroll
        for (int j = 0; j < 64; j++) acc[j] += sMp1[j*22 + m];
    }
    float h1[64];
    #pragma unroll
    for (int j = 0; j < 64; j++) h1[j] = fmaxf(acc[j], 0.f);

    // ---- psi layer 2 folded into a[4] = (psi*m)·Wkq2 ----
    #pragma unroll
    for (int j = 0; j < 64; j++) acc[j] = sbp2[j];
    const float4* sWp2v = (const float4*)sWp2;
    #pragma unroll 8
    for (int c = 0; c < 64; c++) {
        float s = h1[c];
        #pragma unroll
        for (int j4 = 0; j4 < 16; j4++) {
            float4 w = sWp2v[c*16 + j4];
            acc[j4*4+0] += s*w.x; acc[j4*4+1] += s*w.y;
            acc[j4*4+2] += s*w.z; acc[j4*4+3] += s*w.w;
        }
    }
    const float4* sWkqv = (const float4*)sWkq;
    float a0 = 0.f, a1 = 0.f, a2 = 0.f, a3 = 0.f;
    #pragma unroll
    for (int j = 0; j < 64; j++) {
        float ps = fmaxf(acc[j], 0.f) * mk;
        float4 wk = sWkqv[31 + j];
        a0 += ps*wk.x; a1 += ps*wk.y; a2 += ps*wk.z; a3 += ps*wk.w;
    }
    ((float4*)g_a)[idx] = make_float4(a0, a1, a2, a3);

    // ---- xq[4] = x·Wkq1 ----
    float q0 = 0.f, q1 = 0.f, q2 = 0.f, q3 = 0.f;
    #pragma unroll
    for (int r = 0; r < 9; r++) {
        float4 wk = sWkqv[r];
        q0 += x9[r]*wk.x; q1 += x9[r]*wk.y; q2 += x9[r]*wk.z; q3 += x9[r]*wk.w;
    }
    if (ms > 0) {
        float4 wk = sWkqv[8 + ms];
        q0 += wk.x; q1 += wk.y; q2 += wk.z; q3 += wk.w;
    }
    ((float4*)g_xq)[idx] = make_float4(q0, q1, q2, q3);

    // ---- phi MLP ----
    float f1[32];
    {
        float fa[32];
        #pragma unroll
        for (int j = 0; j < 32; j++) fa[j] = sbf1[j];
        const float4* sWf1v = (const float4*)sWf1;
        #pragma unroll
        for (int r = 0; r < 9; r++) {
            float s = x9[r];
            #pragma unroll
            for (int j4 = 0; j4 < 8; j4++) {
                float4 w = sWf1v[r*8 + j4];
                fa[j4*4+0] += s*w.x; fa[j4*4+1] += s*w.y;
                fa[j4*4+2] += s*w.z; fa[j4*4+3] += s*w.w;
            }
        }
        if (ms > 0) {
            int m = ms - 1;
            #pragma unroll
            for (int j = 0; j < 32; j++) fa[j] += sMf1[j*22 + m];
        }
        #pragma unroll
        for (int j = 0; j < 32; j++) f1[j] = fmaxf(fa[j], 0.f);
    }
    {
        float fa[32];
        #pragma unroll
        for (int j = 0; j < 32; j++) fa[j] = sbf2[j];
        const float4* sWf2v = (const float4*)sWf2;
        #pragma unroll 8
        for (int c = 0; c < 32; c++) {
            float s = f1[c];
            #pragma unroll
            for (int j4 = 0; j4 < 8; j4++) {
                float4 w = sWf2v[c*8 + j4];
                fa[j4*4+0] += s*w.x; fa[j4*4+1] += s*w.y;
                fa[j4*4+2] += s*w.z; fa[j4*4+3] += s*w.w;
            }
        }
        float4* phv = (float4*)(g_phi + (size_t)idx*32);
        #pragma unroll
        for (int j4 = 0; j4 < 8; j4++) {
            phv[j4] = make_float4(fmaxf(fa[j4*4+0],0.f)*mk, fmaxf(fa[j4*4+1],0.f)*mk,
                                  fmaxf(fa[j4*4+2],0.f)*mk, fmaxf(fa[j4*4+3],0.f)*mk);
        }
    }
}

// ---------------------------------------------------------------- k_scan
// one 1024-thread block per (batch, head). warp = 32-token chunk, lane = phi channel.
// Parallel scan over the online-softmax monoid (M, S, V[lane]).
__global__ void __launch_bounds__(1024) k_scan(const float* __restrict__ mask) {
    int b = blockIdx.x >> 2;
    int h = blockIdx.x & 3;
    int tid  = threadIdx.x;
    int warp = tid >> 5;
    int lane = tid & 31;
    int base = b * SEQ;
    const float inv_sqrt = 0.17677669529663688f;

    __shared__ float spre[SEQ];
    __shared__ float smk[SEQ];
    __shared__ float wsumA[32], wsumM[32];
    __shared__ float cM[32], cS[32], cV[32*33];
    __shared__ float pM[32], pS[32], pV[32*33];

    // ---- phase 1: block inclusive scan of a and mask -> pre ----
    float a  = g_a [(base+tid)*4 + h];
    float mk = mask[ base+tid ];
    float xq = g_xq[(base+tid)*4 + h];

    float A = a, Sm = mk;
    #pragma unroll
    for (int d = 1; d < 32; d <<= 1) {
        float tA = __shfl_up_sync(0xffffffffu, A, d);
        float tS = __shfl_up_sync(0xffffffffu, Sm, d);
        if (lane >= d) { A += tA; Sm += tS; }
    }
    if (lane == 31) { wsumA[warp] = A; wsumM[warp] = Sm; }
    __syncthreads();
    if (warp == 0) {
        float xA = wsumA[lane], xS = wsumM[lane];
        #pragma unroll
        for (int d = 1; d < 32; d <<= 1) {
            float tA = __shfl_up_sync(0xffffffffu, xA, d);
            float tS = __shfl_up_sync(0xffffffffu, xS, d);
            if (lane >= d) { xA += tA; xS += tS; }
        }
        wsumA[lane] = xA; wsumM[lane] = xS;
    }
    __syncthreads();
    if (warp > 0) { A += wsumA[warp-1]; Sm += wsumM[warp-1]; }

    float pre = (xq + g_bq[h] + __fdividef(A, Sm)) * inv_sqrt;
    spre[tid] = pre;
    smk[tid]  = mk;
    __syncthreads();

    // ---- phase 2: per-warp chunk reduce (cache phi in registers) ----
    float ph[32];
    float M = NEG_BIG, S = 0.f, V = 0.f;
    int p0 = warp * 32;
    #pragma unroll
    for (int i = 0; i < 32; i++) {
        int p = p0 + i;
        float pr = spre[p];
        float f  = g_phi[(size_t)(base + p)*32 + lane];
        ph[i] = f;
        float nM = fmaxf(M, pr);
        float cs = __expf(M - nM);
        float w  = __expf(pr - nM);
        S = S*cs + w;
        V = V*cs + w*f;
        M = nM;
    }
    if (lane == 0) { cM[warp] = M; cS[warp] = S; }
    cV[warp*33 + lane] = V;
    __syncthreads();

    // ---- phase 3: warp 0 exclusive scan over 32 chunk summaries ----
    if (warp == 0) {
        float eM = NEG_BIG, eS = 0.f, eV = 0.f;
        #pragma unroll
        for (int c = 0; c < 32; c++) {
            if (lane == 0) { pM[c] = eM; pS[c] = eS; }
            pV[c*33 + lane] = eV;
            float m2 = cM[c], s2 = cS[c], v2 = cV[c*33 + lane];
            float nM = fmaxf(eM, m2);
            float e1 = __expf(eM - nM);
            float e2 = __expf(m2 - nM);
            eS = eS*e1 + s2*e2;
            eV = eV*e1 + v2*e2;
            eM = nM;
        }
    }
    __syncthreads();

    // ---- phase 4: replay chunk seeded with exclusive prefix, write agg ----
    M = pM[warp]; S = pS[warp]; V = pV[warp*33 + lane];
    #pragma unroll
    for (int i = 0; i < 32; i++) {
        int p = p0 + i;
        float pr = spre[p];
        float nM = fmaxf(M, pr);
        float cs = __expf(M - nM);
        float w  = __expf(pr - nM);
        S = S*cs + w;
        V = V*cs + w*ph[i];
        M = nM;
        g_agg[(size_t)(base + p)*128 + h*32 + lane] = __fdividef(V, S) * smk[p];
    }
}

// ---------------------------------------------------------------- k_rho
// 128 tokens per block, one thread per token. Weights + act tile in dynamic smem.
#define RHO_PAD 132
extern __shared__ float rho_smem[];
__global__ void __launch_bounds__(128) k_rho(
    const float* __restrict__ W1, const float* __restrict__ b1,
    const float* __restrict__ W2, const float* __restrict__ b2,
    const float* __restrict__ mask, float* __restrict__ out)
{
    float* sW1 = rho_smem;                 // 128*64
    float* sW2 = sW1 + 128*64;             // 64*64
    float* sA  = sW2 + 64*64;              // 128*RHO_PAD
    float* sb1 = sA  + 128*RHO_PAD;        // 64
    float* sb2 = sb1 + 64;                 // 64

    int tid  = threadIdx.x;
    int tok0 = blockIdx.x * 128;

    for (int i = tid; i < 128*64; i += 128) sW1[i] = W1[i];
    for (int i = tid; i < 64*64;  i += 128) sW2[i] = W2[i];
    if (tid < 64) { sb1[tid] = b1[tid]; sb2[tid] = b2[tid]; }
    // stage act tile: 128 tokens x 128 k, coalesced float4 loads
    {
        const float4* src = (const float4*)(g_agg + (size_t)tok0*128);
        #pragma unroll 8
        for (int l4 = tid; l4 < 128*32; l4 += 128) {
            int tk = l4 >> 5, k4 = l4 & 31;
            ((float4*)(sA + tk*RHO_PAD))[k4] = src[l4];
        }
    }
    __syncthreads();

    // ---- layer 1: acc[64] over K=128 ----
    float acc[64];
    #pragma unroll
    for (int j = 0; j < 64; j++) acc[j] = 0.f;
    const float4* rowA = (const float4*)(sA + tid*RHO_PAD);
    const float4* sW1v = (const float4*)sW1;
    #pragma unroll 4
    for (int k4 = 0; k4 < 32; k4++) {
        float4 xv = rowA[k4];
        #pragma unroll
        for (int e = 0; e < 4; e++) {
            float s = (e==0)?xv.x:(e==1)?xv.y:(e==2)?xv.z:xv.w;
            int k = k4*4 + e;
            #pragma unroll
            for (int j4 = 0; j4 < 16; j4++) {
                float4 w = sW1v[k*16 + j4];
                acc[j4*4+0] += s*w.x; acc[j4*4+1] += s*w.y;
                acc[j4*4+2] += s*w.z; acc[j4*4+3] += s*w.w;
            }
        }
    }
    float hh[64];
    #pragma unroll
    for (int j = 0; j < 64; j++) hh[j] = fmaxf(acc[j] + sb1[j], 0.f);

    // ---- layer 2: out[64] over K=64 ----
    #pragma unroll
    for (int j = 0; j < 64; j++) acc[j] = sb2[j];
    const float4* sW2v = (const float4*)sW2;
    #pragma unroll 4
    for (int c = 0; c < 64; c++) {
        float s = hh[c];
        #pragma unroll
        for (int j4 = 0; j4 < 16; j4++) {
            float4 w = sW2v[c*16 + j4];
            acc[j4*4+0] += s*w.x; acc[j4*4+1] += s*w.y;
            acc[j4*4+2] += s*w.z; acc[j4*4+3] += s*w.w;
        }
    }
    float mk = mask[tok0 + tid];
    float4* op = (float4*)(out + (size_t)(tok0 + tid)*64);
    #pragma unroll
    for (int j4 = 0; j4 < 16; j4++) {
        op[j4] = make_float4(fmaxf(acc[j4*4+0],0.f)*mk, fmaxf(acc[j4*4+1],0.f)*mk,
                             fmaxf(acc[j4*4+2],0.f)*mk, fmaxf(acc[j4*4+3],0.f)*mk);
    }
}

// ---------------------------------------------------------------- launch
extern "C" void kernel_launch(void* const* d_in, const int* in_sizes, int n_in,
                              void* d_out, int out_size) {
    (void)in_sizes; (void)n_in; (void)out_size;
    const float* times  = (const float*)d_in[0];
    const float* values = (const float*)d_in[1];
    const int*   meas   = (const int*)  d_in[2];
    const float* mask   = (const float*)d_in[3];
    const float* Wp1 = (const float*)d_in[4];  const float* bp1 = (const float*)d_in[5];
    const float* Wp2 = (const float*)d_in[6];  const float* bp2 = (const float*)d_in[7];
    const float* Wk  = (const float*)d_in[8];  const float* bk  = (const float*)d_in[9];
    const float* q   = (const float*)d_in[10];
    const float* Wf1 = (const float*)d_in[11]; const float* bf1 = (const float*)d_in[12];
    const float* Wf2 = (const float*)d_in[13]; const float* bf2 = (const float*)d_in[14];
    const float* Wr1 = (const float*)d_in[15]; const float* br1 = (const float*)d_in[16];
    const float* Wr2 = (const float*)d_in[17]; const float* br2 = (const float*)d_in[18];
    float* out = (float*)d_out;

    size_t rho_bytes = (128*64 + 64*64 + 128*RHO_PAD + 128) * sizeof(float);
    cudaFuncSetAttribute(k_rho, cudaFuncAttributeMaxDynamicSharedMemorySize, (int)rho_bytes);

    k_prep<<<1, 384>>>(Wk, bk, q);
    k_feat<<<128, 128>>>(times, values, meas, mask,
                         Wp1, bp1, Wp2, bp2, Wf1, bf1, Wf2, bf2);
    k_scan<<<BATCH*NH, 1024>>>(mask);
    k_rho<<<128, 128, rho_bytes>>>(Wr1, br1, Wr2, br2, mask, out);
}